// round 2
// baseline (speedup 1.0000x reference)
#include <cuda_runtime.h>

#define N_NODES 100000
#define E_EDGES 1600000
#define D 64
#define PITCH 68     // node-kernel smem pitch
#define PITCH_A 132  // edge-kernel A pitch (128 edges + pad, 16B-aligned)
#define PITCH_B 72   // edge-kernel B pitch (64 outs + pad, 16B-aligned)

// Scratch (device globals — no dynamic allocation allowed)
__device__ float g_acc[2 * N_NODES * D];   // [v-sums | u-sums]
__device__ float g_deg[2 * N_NODES];       // [deg_v | deg_u]
__device__ float g_hweb[N_NODES * D];      // h @ We_h^T + be  (per-node, gathered per-edge)

// ---------------------------------------------------------------------------
// Stage 1: scatter-add efeats into per-node sums (both directions) + degrees
// ---------------------------------------------------------------------------
__device__ __forceinline__ void red_add_v4(float* p, float4 f) {
    asm volatile("red.global.add.v4.f32 [%0], {%1,%2,%3,%4};"
                 :: "l"(p), "f"(f.x), "f"(f.y), "f"(f.z), "f"(f.w) : "memory");
}

__global__ void scatter_kernel(const float4* __restrict__ ef4,
                               const int* __restrict__ u,
                               const int* __restrict__ v) {
    int idx = blockIdx.x * blockDim.x + threadIdx.x;  // exactly E*16
    int e = idx >> 4;
    int c = idx & 15;
    float4 f = ef4[idx];
    int vv = v[e];
    int uu = u[e];
    red_add_v4(&g_acc[(vv << 6) + (c << 2)], f);
    red_add_v4(&g_acc[(N_NODES << 6) + (uu << 6) + (c << 2)], f);
    if (c == 0) {
        atomicAdd(&g_deg[vv], 1.0f);
        atomicAdd(&g_deg[N_NODES + uu], 1.0f);
    }
}

// ---------------------------------------------------------------------------
// Stage 2: per-node — means, h = relu(cat @ Wn^T + bn), hweb = h @ We_h^T + be
// ---------------------------------------------------------------------------
__global__ void node_kernel(const float* __restrict__ Wn,
                            const float* __restrict__ bn,
                            const float* __restrict__ We,
                            const float* __restrict__ be,
                            float* __restrict__ h_out) {
    extern __shared__ float smem[];
    float* A_s = smem;                 // [128][PITCH]
    float* B_s = smem + 128 * PITCH;   // [128][PITCH]

    int t = threadIdx.x;
    int nb = blockIdx.x * 64;

    {
        int nl = t >> 2, q = t & 3;
        int n = nb + nl;
        bool ok = (n < N_NODES);
        float rv = 0.f, ru = 0.f;
        if (ok) {
            rv = 1.0f / fmaxf(g_deg[n], 1.0f);
            ru = 1.0f / fmaxf(g_deg[N_NODES + n], 1.0f);
        }
#pragma unroll
        for (int i = 0; i < 8; i++) {
            int k4 = q + 4 * i;
            float4 f = make_float4(0.f, 0.f, 0.f, 0.f);
            float s = 0.f;
            if (ok) {
                if (k4 < 16) { f = ((const float4*)g_acc)[n * 16 + k4]; s = rv; }
                else         { f = ((const float4*)g_acc)[(N_NODES + n) * 16 + (k4 - 16)]; s = ru; }
            }
            int k = k4 << 2;
            A_s[(k + 0) * PITCH + nl] = f.x * s;
            A_s[(k + 1) * PITCH + nl] = f.y * s;
            A_s[(k + 2) * PITCH + nl] = f.z * s;
            A_s[(k + 3) * PITCH + nl] = f.w * s;
        }
    }
    {
        int o = t >> 2, q = t & 3;
#pragma unroll
        for (int i = 0; i < 8; i++) {
            int k4 = q + 4 * i;
            float4 f = ((const float4*)Wn)[o * 32 + k4];
            int k = k4 << 2;
            B_s[(k + 0) * PITCH + o] = f.x;
            B_s[(k + 1) * PITCH + o] = f.y;
            B_s[(k + 2) * PITCH + o] = f.z;
            B_s[(k + 3) * PITCH + o] = f.w;
        }
    }
    __syncthreads();

    int tx = t & 15, ty = t >> 4;
    float acc[4][4] = {};
#pragma unroll 8
    for (int k = 0; k < 128; k++) {
        float4 a = *reinterpret_cast<const float4*>(&A_s[k * PITCH + (tx << 2)]);
        float4 b = *reinterpret_cast<const float4*>(&B_s[k * PITCH + (ty << 2)]);
        float av[4] = {a.x, a.y, a.z, a.w};
        float bv[4] = {b.x, b.y, b.z, b.w};
#pragma unroll
        for (int i = 0; i < 4; i++)
#pragma unroll
            for (int j = 0; j < 4; j++)
                acc[i][j] = fmaf(av[i], bv[j], acc[i][j]);
    }

    float4 bnv = ((const float4*)bn)[ty];
    float bnb[4] = {bnv.x, bnv.y, bnv.z, bnv.w};
    float hv[4][4];
#pragma unroll
    for (int i = 0; i < 4; i++)
#pragma unroll
        for (int j = 0; j < 4; j++)
            hv[i][j] = fmaxf(acc[i][j] + bnb[j], 0.0f);

    __syncthreads();

    float* C_s = A_s;
    float* H_s = B_s;

#pragma unroll
    for (int i = 0; i < 4; i++) {
        int n = nb + (tx << 2) + i;
#pragma unroll
        for (int j = 0; j < 4; j++)
            H_s[((ty << 2) + j) * PITCH + (tx << 2) + i] = hv[i][j];
        if (n < N_NODES)
            *reinterpret_cast<float4*>(&h_out[n * 64 + (ty << 2)]) =
                make_float4(hv[i][0], hv[i][1], hv[i][2], hv[i][3]);
    }
    {
        int o2 = t >> 2, q = t & 3;
#pragma unroll
        for (int i = 0; i < 4; i++) {
            int k4 = q + 4 * i;
            float4 f = ((const float4*)We)[o2 * 32 + k4];
            int k = k4 << 2;
            C_s[(k + 0) * PITCH + o2] = f.x;
            C_s[(k + 1) * PITCH + o2] = f.y;
            C_s[(k + 2) * PITCH + o2] = f.z;
            C_s[(k + 3) * PITCH + o2] = f.w;
        }
    }
    __syncthreads();

    float acc2[4][4] = {};
#pragma unroll 8
    for (int k = 0; k < 64; k++) {
        float4 a = *reinterpret_cast<const float4*>(&H_s[k * PITCH + (tx << 2)]);
        float4 b = *reinterpret_cast<const float4*>(&C_s[k * PITCH + (ty << 2)]);
        float av[4] = {a.x, a.y, a.z, a.w};
        float bv[4] = {b.x, b.y, b.z, b.w};
#pragma unroll
        for (int i = 0; i < 4; i++)
#pragma unroll
            for (int j = 0; j < 4; j++)
                acc2[i][j] = fmaf(av[i], bv[j], acc2[i][j]);
    }

    float4 bev = ((const float4*)be)[ty];
    float beb[4] = {bev.x, bev.y, bev.z, bev.w};
#pragma unroll
    for (int i = 0; i < 4; i++) {
        int n = nb + (tx << 2) + i;
        if (n < N_NODES)
            *reinterpret_cast<float4*>(&g_hweb[n * 64 + (ty << 2)]) =
                make_float4(acc2[i][0] + beb[0], acc2[i][1] + beb[1],
                            acc2[i][2] + beb[2], acc2[i][3] + beb[3]);
    }
}

// ---------------------------------------------------------------------------
// Stage 3: per-edge — edge = hweb[u[e]] + efeats[e] @ We_e^T
// 128 threads, 128-edge x 64-out tile, 8x8 micro-tile, packed fma.rn.f32x2.
// ---------------------------------------------------------------------------
__device__ __forceinline__ unsigned long long splat2(float a) {
    unsigned long long r;
    asm("mov.b64 %0, {%1, %1};" : "=l"(r) : "f"(a));
    return r;
}
__device__ __forceinline__ void fma2(unsigned long long& acc,
                                     unsigned long long a, unsigned long long b) {
    asm("fma.rn.f32x2 %0, %1, %2, %0;" : "+l"(acc) : "l"(a), "l"(b));
}
__device__ __forceinline__ float2 unpack2(unsigned long long p) {
    float lo, hi;
    asm("mov.b64 {%0, %1}, %2;" : "=f"(lo), "=f"(hi) : "l"(p));
    return make_float2(lo, hi);
}

__global__ void __launch_bounds__(128, 4)
edge_kernel(const float* __restrict__ efeats,
            const int* __restrict__ u,
            const float* __restrict__ We,
            float* __restrict__ edge_out) {
    extern __shared__ float smem[];
    float* A_s = smem;                    // [64][PITCH_A]  A_s[k][e], e<128
    float* B_s = smem + 64 * PITCH_A;     // [64][PITCH_B]  B_s[k][o], o<64
    int* u_s = (int*)(smem + 64 * PITCH_A + 64 * PITCH_B);  // [128]

    int t = threadIdx.x;
    int eb = blockIdx.x * 128;

    u_s[t] = u[eb + t];

    // A fill: thread t owns edge row eb+t; transpose into A_s[k][t]
    {
        const float4* erow = (const float4*)efeats + (size_t)(eb + t) * 16;
#pragma unroll
        for (int i = 0; i < 16; i++) {
            float4 f = erow[i];
            int k = i << 2;
            A_s[(k + 0) * PITCH_A + t] = f.x;
            A_s[(k + 1) * PITCH_A + t] = f.y;
            A_s[(k + 2) * PITCH_A + t] = f.z;
            A_s[(k + 3) * PITCH_A + t] = f.w;
        }
    }
    // B fill: We_e = We[:, 64:128] transposed -> B_s[k][o]
    {
        int o = t & 63, half = t >> 6;
        const float4* wrow = (const float4*)We + o * 32 + 16 + half * 8;
#pragma unroll
        for (int i = 0; i < 8; i++) {
            float4 f = wrow[i];
            int k = (half * 8 + i) << 2;
            B_s[(k + 0) * PITCH_B + o] = f.x;
            B_s[(k + 1) * PITCH_B + o] = f.y;
            B_s[(k + 2) * PITCH_B + o] = f.z;
            B_s[(k + 3) * PITCH_B + o] = f.w;
        }
    }
    __syncthreads();

    int tx = t & 15;   // edge group: edges tx*8 .. tx*8+7
    int ty = t >> 4;   // out group:  outs  ty*8 .. ty*8+7

    unsigned long long acc[8][4];
#pragma unroll
    for (int i = 0; i < 8; i++)
#pragma unroll
        for (int j = 0; j < 4; j++) acc[i][j] = 0ull;

#pragma unroll 8
    for (int k = 0; k < 64; k++) {
        const float* arow = &A_s[k * PITCH_A + (tx << 3)];
        float4 a0 = *reinterpret_cast<const float4*>(arow);
        float4 a1 = *reinterpret_cast<const float4*>(arow + 4);
        const float* brow = &B_s[k * PITCH_B + (ty << 3)];
        ulonglong2 b0 = *reinterpret_cast<const ulonglong2*>(brow);       // pairs (o0,o1),(o2,o3)
        ulonglong2 b1 = *reinterpret_cast<const ulonglong2*>(brow + 4);   // pairs (o4,o5),(o6,o7)
        unsigned long long bp[4] = {b0.x, b0.y, b1.x, b1.y};
        float av[8] = {a0.x, a0.y, a0.z, a0.w, a1.x, a1.y, a1.z, a1.w};
#pragma unroll
        for (int i = 0; i < 8; i++) {
            unsigned long long as = splat2(av[i]);
#pragma unroll
            for (int j = 0; j < 4; j++)
                fma2(acc[i][j], as, bp[j]);
        }
    }

    // Epilogue: add gathered hweb[u[e]] and store
#pragma unroll
    for (int i = 0; i < 8; i++) {
        int el = (tx << 3) + i;
        size_t e = (size_t)(eb + el);
        int uu = u_s[el];
        const float4* g = (const float4*)&g_hweb[uu * 64 + (ty << 3)];
        float4 g0 = g[0], g1 = g[1];
        float2 c0 = unpack2(acc[i][0]);
        float2 c1 = unpack2(acc[i][1]);
        float2 c2 = unpack2(acc[i][2]);
        float2 c3 = unpack2(acc[i][3]);
        float4* outp = (float4*)&edge_out[e * 64 + (ty << 3)];
        outp[0] = make_float4(c0.x + g0.x, c0.y + g0.y, c1.x + g0.z, c1.y + g0.w);
        outp[1] = make_float4(c2.x + g1.x, c2.y + g1.y, c3.x + g1.z, c3.y + g1.w);
    }
}

// ---------------------------------------------------------------------------
extern "C" void kernel_launch(void* const* d_in, const int* in_sizes, int n_in,
                              void* d_out, int out_size) {
    // inputs: [0]=nfeats (unused), [1]=efeats, [2]=u, [3]=v, [4]=Wn, [5]=bn, [6]=We, [7]=be
    const float* efeats = (const float*)d_in[1];
    const int*   u      = (const int*)d_in[2];
    const int*   v      = (const int*)d_in[3];
    const float* Wn     = (const float*)d_in[4];
    const float* bn     = (const float*)d_in[5];
    const float* We     = (const float*)d_in[6];
    const float* be     = (const float*)d_in[7];

    float* out      = (float*)d_out;
    float* h_out    = out;                               // [N,64]
    float* edge_out = out + (size_t)N_NODES * 64;        // [E,64]

    void* accp = nullptr; cudaGetSymbolAddress(&accp, g_acc);
    void* degp = nullptr; cudaGetSymbolAddress(&degp, g_deg);
    cudaMemsetAsync(accp, 0, sizeof(float) * 2 * N_NODES * D, 0);
    cudaMemsetAsync(degp, 0, sizeof(float) * 2 * N_NODES, 0);

    scatter_kernel<<<(E_EDGES * 16) / 256, 256>>>((const float4*)efeats, u, v);

    int node_smem = 2 * 128 * PITCH * (int)sizeof(float);  // 69632 B
    cudaFuncSetAttribute(node_kernel, cudaFuncAttributeMaxDynamicSharedMemorySize, node_smem);
    node_kernel<<<(N_NODES + 63) / 64, 256, node_smem>>>(Wn, bn, We, be, h_out);

    int edge_smem = (64 * PITCH_A + 64 * PITCH_B + 128) * (int)sizeof(float);  // 52736 B
    cudaFuncSetAttribute(edge_kernel, cudaFuncAttributeMaxDynamicSharedMemorySize, edge_smem);
    edge_kernel<<<E_EDGES / 128, 128, edge_smem>>>(efeats, u, We, edge_out);
}

// round 3
// speedup vs baseline: 1.2331x; 1.2331x over previous
#include <cuda_runtime.h>

#define N_NODES 100000
#define E_EDGES 1600000
#define D 64
#define PITCH 68     // node-kernel smem pitch
#define EPITCH 68    // edge-kernel smem pitch (bank-conflict-free for frag loads)

// Scratch (device globals — no dynamic allocation allowed)
__device__ float g_acc[2 * N_NODES * D];   // [v-sums | u-sums]
__device__ float g_deg[2 * N_NODES];       // [deg_v | deg_u]
__device__ float g_hweb[N_NODES * D];      // h @ We_h^T + be

// ---------------------------------------------------------------------------
// Stage 1: scatter-add efeats into per-node sums (both directions) + degrees
// ---------------------------------------------------------------------------
__device__ __forceinline__ void red_add_v4(float* p, float4 f) {
    asm volatile("red.global.add.v4.f32 [%0], {%1,%2,%3,%4};"
                 :: "l"(p), "f"(f.x), "f"(f.y), "f"(f.z), "f"(f.w) : "memory");
}

__global__ void scatter_kernel(const float4* __restrict__ ef4,
                               const int* __restrict__ u,
                               const int* __restrict__ v) {
    int idx = blockIdx.x * blockDim.x + threadIdx.x;  // exactly E*16
    int e = idx >> 4;
    int c = idx & 15;
    float4 f = ef4[idx];
    int vv = v[e];
    int uu = u[e];
    red_add_v4(&g_acc[(vv << 6) + (c << 2)], f);
    red_add_v4(&g_acc[(N_NODES << 6) + (uu << 6) + (c << 2)], f);
    if (c == 0) {
        atomicAdd(&g_deg[vv], 1.0f);
        atomicAdd(&g_deg[N_NODES + uu], 1.0f);
    }
}

// ---------------------------------------------------------------------------
// Stage 2: per-node — means, h = relu(cat @ Wn^T + bn), hweb = h @ We_h^T + be
// (unchanged from R1: ~65us, not the bottleneck)
// ---------------------------------------------------------------------------
__global__ void node_kernel(const float* __restrict__ Wn,
                            const float* __restrict__ bn,
                            const float* __restrict__ We,
                            const float* __restrict__ be,
                            float* __restrict__ h_out) {
    extern __shared__ float smem[];
    float* A_s = smem;                 // [128][PITCH]
    float* B_s = smem + 128 * PITCH;   // [128][PITCH]

    int t = threadIdx.x;
    int nb = blockIdx.x * 64;

    {
        int nl = t >> 2, q = t & 3;
        int n = nb + nl;
        bool ok = (n < N_NODES);
        float rv = 0.f, ru = 0.f;
        if (ok) {
            rv = 1.0f / fmaxf(g_deg[n], 1.0f);
            ru = 1.0f / fmaxf(g_deg[N_NODES + n], 1.0f);
        }
#pragma unroll
        for (int i = 0; i < 8; i++) {
            int k4 = q + 4 * i;
            float4 f = make_float4(0.f, 0.f, 0.f, 0.f);
            float s = 0.f;
            if (ok) {
                if (k4 < 16) { f = ((const float4*)g_acc)[n * 16 + k4]; s = rv; }
                else         { f = ((const float4*)g_acc)[(N_NODES + n) * 16 + (k4 - 16)]; s = ru; }
            }
            int k = k4 << 2;
            A_s[(k + 0) * PITCH + nl] = f.x * s;
            A_s[(k + 1) * PITCH + nl] = f.y * s;
            A_s[(k + 2) * PITCH + nl] = f.z * s;
            A_s[(k + 3) * PITCH + nl] = f.w * s;
        }
    }
    {
        int o = t >> 2, q = t & 3;
#pragma unroll
        for (int i = 0; i < 8; i++) {
            int k4 = q + 4 * i;
            float4 f = ((const float4*)Wn)[o * 32 + k4];
            int k = k4 << 2;
            B_s[(k + 0) * PITCH + o] = f.x;
            B_s[(k + 1) * PITCH + o] = f.y;
            B_s[(k + 2) * PITCH + o] = f.z;
            B_s[(k + 3) * PITCH + o] = f.w;
        }
    }
    __syncthreads();

    int tx = t & 15, ty = t >> 4;
    float acc[4][4] = {};
#pragma unroll 8
    for (int k = 0; k < 128; k++) {
        float4 a = *reinterpret_cast<const float4*>(&A_s[k * PITCH + (tx << 2)]);
        float4 b = *reinterpret_cast<const float4*>(&B_s[k * PITCH + (ty << 2)]);
        float av[4] = {a.x, a.y, a.z, a.w};
        float bv[4] = {b.x, b.y, b.z, b.w};
#pragma unroll
        for (int i = 0; i < 4; i++)
#pragma unroll
            for (int j = 0; j < 4; j++)
                acc[i][j] = fmaf(av[i], bv[j], acc[i][j]);
    }

    float4 bnv = ((const float4*)bn)[ty];
    float bnb[4] = {bnv.x, bnv.y, bnv.z, bnv.w};
    float hv[4][4];
#pragma unroll
    for (int i = 0; i < 4; i++)
#pragma unroll
        for (int j = 0; j < 4; j++)
            hv[i][j] = fmaxf(acc[i][j] + bnb[j], 0.0f);

    __syncthreads();

    float* C_s = A_s;
    float* H_s = B_s;

#pragma unroll
    for (int i = 0; i < 4; i++) {
        int n = nb + (tx << 2) + i;
#pragma unroll
        for (int j = 0; j < 4; j++)
            H_s[((ty << 2) + j) * PITCH + (tx << 2) + i] = hv[i][j];
        if (n < N_NODES)
            *reinterpret_cast<float4*>(&h_out[n * 64 + (ty << 2)]) =
                make_float4(hv[i][0], hv[i][1], hv[i][2], hv[i][3]);
    }
    {
        int o2 = t >> 2, q = t & 3;
#pragma unroll
        for (int i = 0; i < 4; i++) {
            int k4 = q + 4 * i;
            float4 f = ((const float4*)We)[o2 * 32 + k4];
            int k = k4 << 2;
            C_s[(k + 0) * PITCH + o2] = f.x;
            C_s[(k + 1) * PITCH + o2] = f.y;
            C_s[(k + 2) * PITCH + o2] = f.z;
            C_s[(k + 3) * PITCH + o2] = f.w;
        }
    }
    __syncthreads();

    float acc2[4][4] = {};
#pragma unroll 8
    for (int k = 0; k < 64; k++) {
        float4 a = *reinterpret_cast<const float4*>(&H_s[k * PITCH + (tx << 2)]);
        float4 b = *reinterpret_cast<const float4*>(&C_s[k * PITCH + (ty << 2)]);
        float av[4] = {a.x, a.y, a.z, a.w};
        float bv[4] = {b.x, b.y, b.z, b.w};
#pragma unroll
        for (int i = 0; i < 4; i++)
#pragma unroll
            for (int j = 0; j < 4; j++)
                acc2[i][j] = fmaf(av[i], bv[j], acc2[i][j]);
    }

    float4 bev = ((const float4*)be)[ty];
    float beb[4] = {bev.x, bev.y, bev.z, bev.w};
#pragma unroll
    for (int i = 0; i < 4; i++) {
        int n = nb + (tx << 2) + i;
        if (n < N_NODES)
            *reinterpret_cast<float4*>(&g_hweb[n * 64 + (ty << 2)]) =
                make_float4(acc2[i][0] + beb[0], acc2[i][1] + beb[1],
                            acc2[i][2] + beb[2], acc2[i][3] + beb[3]);
    }
}

// ---------------------------------------------------------------------------
// Stage 3: per-edge — edge = hweb[u[e]] + efeats[e] @ We_e^T  (3xTF32 mma)
// 256 threads (8 warps: 4m x 2n), 128-edge x 64-out block tile.
// Each warp: 32x32 via m16n8k8 tiles, 3-pass tf32 split for fp32 accuracy.
// ---------------------------------------------------------------------------
__device__ __forceinline__ unsigned cvt_tf32(float x) {
    unsigned r;
    asm("cvt.rna.tf32.f32 %0, %1;" : "=r"(r) : "f"(x));
    return r;
}
__device__ __forceinline__ void mma_tf32(float c[4], const unsigned a[4], const unsigned b[2]) {
    asm volatile(
        "mma.sync.aligned.m16n8k8.row.col.f32.tf32.tf32.f32 "
        "{%0,%1,%2,%3}, {%4,%5,%6,%7}, {%8,%9}, {%0,%1,%2,%3};"
        : "+f"(c[0]), "+f"(c[1]), "+f"(c[2]), "+f"(c[3])
        : "r"(a[0]), "r"(a[1]), "r"(a[2]), "r"(a[3]), "r"(b[0]), "r"(b[1]));
}

__global__ void __launch_bounds__(256, 2)
edge_kernel(const float* __restrict__ efeats,
            const int* __restrict__ u,
            const float* __restrict__ We,
            float* __restrict__ edge_out) {
    extern __shared__ float smem[];
    float* A_s  = smem;                    // [128][EPITCH]  efeats rows (fp32)
    float* Bh_s = smem + 128 * EPITCH;     // [64][EPITCH]   We_e hi (tf32 values)
    float* Bl_s = Bh_s + 64 * EPITCH;      // [64][EPITCH]   We_e lo (tf32 values)
    int*   u_s  = (int*)(Bl_s + 64 * EPITCH);  // [128]

    int t = threadIdx.x;
    int eb = blockIdx.x * 128;

    if (t < 128) u_s[t] = u[eb + t];

    // A fill: row-major copy, thread t does half a row (32 floats)
    {
        int e = t >> 1, half = t & 1;
        const float4* erow = (const float4*)efeats + (size_t)(eb + e) * 16 + half * 8;
        float4* dst = (float4*)&A_s[e * EPITCH + half * 32];
#pragma unroll
        for (int i = 0; i < 8; i++) dst[i] = erow[i];
    }
    // B fill: We_e = We[:, 64:128], split into tf32 hi/lo
    {
        int o = t >> 2, q = t & 3;
        const float4* wrow = (const float4*)We + o * 32 + 16 + q * 4;
#pragma unroll
        for (int i = 0; i < 4; i++) {
            float4 f = wrow[i];
            int k = (q * 4 + i) * 4;
            float hx = __uint_as_float(cvt_tf32(f.x));
            float hy = __uint_as_float(cvt_tf32(f.y));
            float hz = __uint_as_float(cvt_tf32(f.z));
            float hw = __uint_as_float(cvt_tf32(f.w));
            *(float4*)&Bh_s[o * EPITCH + k] = make_float4(hx, hy, hz, hw);
            *(float4*)&Bl_s[o * EPITCH + k] = make_float4(
                __uint_as_float(cvt_tf32(f.x - hx)),
                __uint_as_float(cvt_tf32(f.y - hy)),
                __uint_as_float(cvt_tf32(f.z - hz)),
                __uint_as_float(cvt_tf32(f.w - hw)));
        }
    }
    __syncthreads();

    int wid = t >> 5, lane = t & 31;
    int wm = wid & 3;        // edges wm*32 .. +31
    int wn = wid >> 2;       // outs  wn*32 .. +31
    int g  = lane >> 2;      // group id (0..7)
    int tg = lane & 3;       // thread in group (0..3)

    float c[2][4][4] = {};   // [m-tile][n-tile][frag]

#pragma unroll
    for (int ks = 0; ks < 8; ks++) {
        int k0 = ks * 8;
        // A fragments (2 m-tiles), split hi/lo in registers
        unsigned ah[2][4], al[2][4];
#pragma unroll
        for (int mt = 0; mt < 2; mt++) {
            int rb = wm * 32 + mt * 16;
            float a0 = A_s[(rb + g) * EPITCH + k0 + tg];
            float a1 = A_s[(rb + g + 8) * EPITCH + k0 + tg];
            float a2 = A_s[(rb + g) * EPITCH + k0 + tg + 4];
            float a3 = A_s[(rb + g + 8) * EPITCH + k0 + tg + 4];
            ah[mt][0] = cvt_tf32(a0); al[mt][0] = cvt_tf32(a0 - __uint_as_float(ah[mt][0]));
            ah[mt][1] = cvt_tf32(a1); al[mt][1] = cvt_tf32(a1 - __uint_as_float(ah[mt][1]));
            ah[mt][2] = cvt_tf32(a2); al[mt][2] = cvt_tf32(a2 - __uint_as_float(ah[mt][2]));
            ah[mt][3] = cvt_tf32(a3); al[mt][3] = cvt_tf32(a3 - __uint_as_float(ah[mt][3]));
        }
        // B fragments (4 n-tiles)
        unsigned bh[4][2], bl[4][2];
#pragma unroll
        for (int nt = 0; nt < 4; nt++) {
            int n = wn * 32 + nt * 8 + g;
            bh[nt][0] = __float_as_uint(Bh_s[n * EPITCH + k0 + tg]);
            bh[nt][1] = __float_as_uint(Bh_s[n * EPITCH + k0 + tg + 4]);
            bl[nt][0] = __float_as_uint(Bl_s[n * EPITCH + k0 + tg]);
            bl[nt][1] = __float_as_uint(Bl_s[n * EPITCH + k0 + tg + 4]);
        }
#pragma unroll
        for (int mt = 0; mt < 2; mt++)
#pragma unroll
            for (int nt = 0; nt < 4; nt++) {
                mma_tf32(c[mt][nt], ah[mt], bh[nt]);  // hi*hi
                mma_tf32(c[mt][nt], ah[mt], bl[nt]);  // hi*lo
                mma_tf32(c[mt][nt], al[mt], bh[nt]);  // lo*hi
            }
    }

    // Epilogue: c frag (r, 2tg..2tg+1) and (r+8, same), add hweb gather, store
#pragma unroll
    for (int mt = 0; mt < 2; mt++) {
        int r0 = wm * 32 + mt * 16 + g;   // local edge row
        int r1 = r0 + 8;
        int u0 = u_s[r0], u1 = u_s[r1];
        size_t e0 = (size_t)(eb + r0), e1 = (size_t)(eb + r1);
#pragma unroll
        for (int nt = 0; nt < 4; nt++) {
            int col = wn * 32 + nt * 8 + 2 * tg;
            float2 g0 = *(const float2*)&g_hweb[u0 * 64 + col];
            float2 g1 = *(const float2*)&g_hweb[u1 * 64 + col];
            *(float2*)&edge_out[e0 * 64 + col] =
                make_float2(c[mt][nt][0] + g0.x, c[mt][nt][1] + g0.y);
            *(float2*)&edge_out[e1 * 64 + col] =
                make_float2(c[mt][nt][2] + g1.x, c[mt][nt][3] + g1.y);
        }
    }
}

// ---------------------------------------------------------------------------
extern "C" void kernel_launch(void* const* d_in, const int* in_sizes, int n_in,
                              void* d_out, int out_size) {
    // inputs: [0]=nfeats (unused), [1]=efeats, [2]=u, [3]=v, [4]=Wn, [5]=bn, [6]=We, [7]=be
    const float* efeats = (const float*)d_in[1];
    const int*   u      = (const int*)d_in[2];
    const int*   v      = (const int*)d_in[3];
    const float* Wn     = (const float*)d_in[4];
    const float* bn     = (const float*)d_in[5];
    const float* We     = (const float*)d_in[6];
    const float* be     = (const float*)d_in[7];

    float* out      = (float*)d_out;
    float* h_out    = out;                               // [N,64]
    float* edge_out = out + (size_t)N_NODES * 64;        // [E,64]

    void* accp = nullptr; cudaGetSymbolAddress(&accp, g_acc);
    void* degp = nullptr; cudaGetSymbolAddress(&degp, g_deg);
    cudaMemsetAsync(accp, 0, sizeof(float) * 2 * N_NODES * D, 0);
    cudaMemsetAsync(degp, 0, sizeof(float) * 2 * N_NODES, 0);

    scatter_kernel<<<(E_EDGES * 16) / 256, 256>>>((const float4*)efeats, u, v);

    int node_smem = 2 * 128 * PITCH * (int)sizeof(float);  // 69632 B
    cudaFuncSetAttribute(node_kernel, cudaFuncAttributeMaxDynamicSharedMemorySize, node_smem);
    node_kernel<<<(N_NODES + 63) / 64, 256, node_smem>>>(Wn, bn, We, be, h_out);

    int edge_smem = (128 * EPITCH + 2 * 64 * EPITCH) * (int)sizeof(float) + 128 * (int)sizeof(int);
    cudaFuncSetAttribute(edge_kernel, cudaFuncAttributeMaxDynamicSharedMemorySize, edge_smem);
    edge_kernel<<<E_EDGES / 128, 256, edge_smem>>>(efeats, u, We, edge_out);
}